// round 12
// baseline (speedup 1.0000x reference)
#include <cuda_runtime.h>
#include <cuda_bf16.h>
#include <cstdint>

#define NPTS 2048
#define DIMS 96
#define NTH 1024
#define THRESH 64
#define EG 64
#define MAXP 1024
#define TILE 32
#define RECIPN (NPTS + 1)

// Device scratch (no runtime allocation allowed)
__device__ double g_d2[(size_t)NPTS * NPTS];      // 32 MB
__device__ double g_sq[NPTS];
__device__ long long g_sqi[NPTS];
__device__ unsigned g_k[NPTS * DIMS];             // x * 2^23 (exact integers)
__device__ int    g_exact;
__device__ double g_recip[RECIPN];
__device__ int    g_nn[NPTS];
__device__ double g_nnd[NPTS];
__device__ int    g_parent[NPTS];
__device__ int    g_active[NPTS];
__device__ int    g_rank[NPTS];
__device__ double g_md[NPTS];
__device__ int    g_mj[NPTS];
__device__ int    g_mcnt;
__device__ unsigned g_arrive;
__device__ volatile unsigned g_release;

__device__ __forceinline__ double dinf() {
    return __longlong_as_double(0x7ff0000000000000LL);
}

// Markstein correctly-rounded division num/T given r = RN(1/T): returns RN(num/T).
__device__ __forceinline__ double div_exact(double num, double T, double r) {
    double q0 = __dmul_rn(num, r);
    double e  = __fma_rn(-T, q0, num);
    return __fma_rn(e, r, q0);
}

// sense-reversal software grid barrier (all blocks co-resident by construction)
// __threadfence (gpu scope) also flushes L1D -> cross-SM d2 reads stay coherent.
__device__ __forceinline__ void grid_bar() {
    __syncthreads();
    if (threadIdx.x == 0) {
        __threadfence();
        unsigned gen = g_release;
        if (atomicAdd(&g_arrive, 1) == gridDim.x - 1) {
            atomicExch(&g_arrive, 0);
            __threadfence();
            g_release = gen + 1;
        } else {
            while (*(volatile unsigned*)&g_release == gen) { }
        }
        __threadfence();
    }
    __syncthreads();
}

// ---------------------------------------------------------------------------
__global__ void k_init_sq(const float* __restrict__ x) {
    int i = blockIdx.x * blockDim.x + threadIdx.x;
    if (i >= NPTS) return;
    g_recip[i + 1] = 1.0 / (double)(i + 1);
    if (i == 0) { g_recip[0] = 1.0; g_mcnt = 0; g_arrive = 0; g_release = 0; g_exact = 1; }
    const float* xr = x + (size_t)i * DIMS;
    double acc = 0.0;
    long long acci = 0;
    bool ok = true;
    #pragma unroll 8
    for (int d = 0; d < DIMS; d++) {
        const float xv = xr[d];
        double v = (double)xv;
        acc = fma(v, v, acc);
        unsigned k = (unsigned)(xv * 8388608.0f);
        if (k >= (1u << 23) || (float)k * (1.0f / 8388608.0f) != xv) ok = false;
        g_k[i * DIMS + d] = k;
        acci += (long long)k * (long long)k;
    }
    g_sq[i] = acc;
    g_sqi[i] = acci;
    if (!ok) atomicExch(&g_exact, 0);
    g_parent[i] = i;
    g_active[i] = 1;
}

// ---------------------------------------------------------------------------
// Distance matrix: exact int64 Gram fast path; proven fp64 fallback.
// ---------------------------------------------------------------------------
__global__ void k_init_d2(const float* __restrict__ x) {
    __shared__ unsigned SBUF[2][TILE][DIMS + 1];
    const int ti = blockIdx.y, tj = blockIdx.x;
    if (tj < ti) return;

    if (g_exact) {
        unsigned (*A)[DIMS + 1] = SBUF[0];
        unsigned (*B)[DIMS + 1] = SBUF[1];
        for (int idx = threadIdx.x; idx < TILE * DIMS; idx += blockDim.x) {
            const int r = idx / DIMS, d = idx - r * DIMS;
            A[r][d] = g_k[(size_t)(ti * TILE + r) * DIMS + d];
            B[r][d] = g_k[(size_t)(tj * TILE + r) * DIMS + d];
        }
        __syncthreads();
        const int r0 = (threadIdx.x >> 4) << 1;
        const int c0 = (threadIdx.x & 15) << 1;
        unsigned long long d00 = 0, d01 = 0, d10 = 0, d11 = 0;
        #pragma unroll 8
        for (int d = 0; d < DIMS; d++) {
            const unsigned a0 = A[r0][d], a1 = A[r0 + 1][d];
            const unsigned b0 = B[c0][d], b1 = B[c0 + 1][d];
            d00 += (unsigned long long)a0 * b0;
            d01 += (unsigned long long)a0 * b1;
            d10 += (unsigned long long)a1 * b0;
            d11 += (unsigned long long)a1 * b1;
        }
        #pragma unroll
        for (int rr = 0; rr < 2; rr++) {
            #pragma unroll
            for (int cc = 0; cc < 2; cc++) {
                const int gi = ti * TILE + r0 + rr;
                const int gj = tj * TILE + c0 + cc;
                if (gj < gi) continue;
                double v;
                if (gi == gj) v = dinf();
                else {
                    const unsigned long long dot =
                        (rr == 0) ? (cc == 0 ? d00 : d01) : (cc == 0 ? d10 : d11);
                    const long long num = g_sqi[gi] + g_sqi[gj] - 2ll * (long long)dot;
                    v = (double)num * 0x1p-46;
                }
                g_d2[(size_t)gi * NPTS + gj] = v;
                g_d2[(size_t)gj * NPTS + gi] = v;
            }
        }
    } else {
        float (*A)[DIMS + 1] = reinterpret_cast<float (*)[DIMS + 1]>(SBUF[0]);
        float (*B)[DIMS + 1] = reinterpret_cast<float (*)[DIMS + 1]>(SBUF[1]);
        for (int idx = threadIdx.x; idx < TILE * DIMS; idx += blockDim.x) {
            const int r = idx / DIMS, d = idx - r * DIMS;
            A[r][d] = x[(size_t)(ti * TILE + r) * DIMS + d];
            B[r][d] = x[(size_t)(tj * TILE + r) * DIMS + d];
        }
        __syncthreads();
        #pragma unroll
        for (int e = 0; e < (TILE * TILE) / 256; e++) {
            const int idx = threadIdx.x + e * 256;
            const int r = idx >> 5, c = idx & 31;
            const int gi = ti * TILE + r, gj = tj * TILE + c;
            if (gj < gi) continue;
            if (gi == gj) { g_d2[(size_t)gi * NPTS + gj] = dinf(); continue; }
            double dot = 0.0;
            #pragma unroll 8
            for (int d = 0; d < DIMS; d++) {
                dot = fma((double)A[r][d], (double)B[c][d], dot);
            }
            double v = g_sq[gi] + g_sq[gj] - 2.0 * dot;
            if (v < 0.0) v = 0.0;
            g_d2[(size_t)gi * NPTS + gj] = v;
            g_d2[(size_t)gj * NPTS + gi] = v;
        }
    }
}

// ---------------------------------------------------------------------------
// Persistent RNN-rounds kernel. Grid phase on all SMs; all-smem slot endgame.
// ---------------------------------------------------------------------------
__global__ void __launch_bounds__(NTH, 1) k_rnn(float* __restrict__ out, int K) {
    // Time-multiplexed pool:
    //  grid phase : s_pia[0,2K) s_pja[2K,4K) s_mg[4K,6K) | s_a[16K) s_b[20K) s_id[24K)
    //  endgame    : sd2 doubles [0, 33280)
    //  tail       : s_d [0,16K) | s_a[16K) s_b[20K)
    __shared__ __align__(16) char POOL[EG * (EG + 1) * 8];   // 33280 B
    __shared__ short s_alist[NPTS];                  // 4 KB
    __shared__ unsigned short s_sizes[NPTS];         // 4 KB
    __shared__ int   s_wcnt[64], s_woff[64];
    __shared__ int   s_np, s_na, s_live;
    // endgame small state
    __shared__ short  eg_id[EG];
    __shared__ int    eg_sz[EG];
    __shared__ int    eg_nn[EG];
    __shared__ double eg_nnd[EG];
    __shared__ unsigned char eg_live[EG], eg_mg[EG];
    __shared__ short  eg_pia[EG / 2], eg_pja[EG / 2];

    short* s_pia = (short*)POOL;                     // grid phase
    short* s_pja = (short*)(POOL + 2048);
    unsigned char* s_mg = (unsigned char*)(POOL + 4096);
    double* s_d = (double*)POOL;                     // tail
    int* s_a = (int*)(POOL + 16384);
    int* s_b = (int*)(POOL + 20480);
    short* s_id = (short*)(POOL + 24576);
    double (*sd2)[EG + 1] = (double (*)[EG + 1])POOL;  // endgame

    const int t = threadIdx.x;
    const int w = t >> 5, lane = t & 31;
    const int gtid = blockIdx.x * NTH + t;
    const int gstride = gridDim.x * NTH;
    const int gwarp = blockIdx.x * 32 + w;
    const int nwarps = gridDim.x * 32;
    const double INF = dinf();

    for (int r = t; r < NPTS; r += NTH) { s_alist[r] = (short)r; s_sizes[r] = 1; }
    if (t == 0) s_na = NPTS;
    __syncthreads();

    // ================= grid-wide rounds =================
    while (true) {
        const int na = s_na;
        if (na <= THRESH) break;

        // ---- NN (warp per row) ----
        for (int r = gwarp; r < na; r += nwarps) {
            const int a = (int)s_alist[r];
            const double* row = g_d2 + (size_t)a * NPTS;
            long long bv = 0x7ff0000000000000LL; int bc = NPTS;
            for (int c = lane; c < na; c += 32) {
                const int id = (int)s_alist[c];
                const long long v = __double_as_longlong(row[id]);
                if (v < bv || (v == bv && id < bc)) { bv = v; bc = id; }
            }
            #pragma unroll
            for (int o = 16; o > 0; o >>= 1) {
                long long ov = __shfl_down_sync(0xffffffffu, bv, o);
                int       oc = __shfl_down_sync(0xffffffffu, bc, o);
                if (ov < bv || (ov == bv && oc < bc)) { bv = ov; bc = oc; }
            }
            if (lane == 0) { g_nn[a] = bc; g_nnd[a] = __longlong_as_double(bv); }
        }
        grid_bar();

        // ---- pairs (redundant deterministic per block) ----
        {
            bool p0 = false, p1 = false;
            int a0 = 0, b0 = 0, a1 = 0, b1 = 0;
            if (t < na) {
                a0 = (int)s_alist[t]; b0 = g_nn[a0];
                const bool mut = (g_nn[b0] == a0);
                p0 = mut && (a0 < b0);
                s_mg[t] = (unsigned char)mut;
            }
            const int t2 = t + NTH;
            if (t2 < na) {
                a1 = (int)s_alist[t2]; b1 = g_nn[a1];
                const bool mut = (g_nn[b1] == a1);
                p1 = mut && (a1 < b1);
                s_mg[t2] = (unsigned char)mut;
            }
            const unsigned m0 = __ballot_sync(0xffffffffu, p0);
            const unsigned m1 = __ballot_sync(0xffffffffu, p1);
            if (lane == 0) { s_wcnt[w] = __popc(m0); s_wcnt[32 + w] = __popc(m1); }
            __syncthreads();
            if (t == 0) {
                int acc = 0;
                #pragma unroll
                for (int q = 0; q < 64; q++) { s_woff[q] = acc; acc += s_wcnt[q]; }
                s_np = acc;
            }
            __syncthreads();
            if (p0) {
                const int pos = s_woff[w] + __popc(m0 & ((1u << lane) - 1u));
                s_pia[pos] = (short)a0; s_pja[pos] = (short)b0;
            }
            if (p1) {
                const int pos = s_woff[32 + w] + __popc(m1 & ((1u << lane) - 1u));
                s_pia[pos] = (short)a1; s_pja[pos] = (short)b1;
            }
            __syncthreads();
        }
        const int np = s_np;

        if (blockIdx.x == 0) {
            const int mbase = g_mcnt;
            for (int p = t; p < np; p += NTH) {
                const int ia = (int)s_pia[p], ja = (int)s_pja[p];
                g_parent[ja] = ia;
                g_md[mbase + p] = g_nnd[ia];
                g_mj[mbase + p] = ja;
            }
            __syncthreads();
            if (t == 0) g_mcnt = mbase + np;
        }

        // ---- Lance-Williams: (pair x unmerged) + same-round cross ----
        {
            const long long tot1 = (long long)np * na;
            for (long long xw = gtid; xw < tot1; xw += gstride) {
                const int p = (int)(xw / na);
                const int idx = (int)(xw - (long long)p * na);
                if (s_mg[idx]) continue;
                const int m = (int)s_alist[idx];
                const int iA = (int)s_pia[p], jA = (int)s_pja[p];
                const int szi = (int)s_sizes[iA], szj = (int)s_sizes[jA], szm = (int)s_sizes[m];
                const double si = (double)szi, sj = (double)szj;
                const double dij = g_nnd[iA];
                const double sm = (double)szm;
                const double a = g_d2[(size_t)iA * NPTS + m];
                const double b = g_d2[(size_t)jA * NPTS + m];
                const int Ti = szi + szj + szm;
                const double num = ((si + sm) * a + (sj + sm) * b - sm * dij);
                const double nd = div_exact(num, (double)Ti, __ldg(&g_recip[Ti]));
                g_d2[(size_t)iA * NPTS + m] = nd;
                g_d2[(size_t)m * NPTS + iA] = nd;
            }
            const long long tot2 = (long long)np * np;
            for (long long xw = gtid; xw < tot2; xw += gstride) {
                const int p = (int)(xw / np);
                const int q = (int)(xw - (long long)p * np);
                if (p >= q) continue;
                const double dp = g_nnd[(int)s_pia[p]], dq = g_nnd[(int)s_pia[q]];
                int e, l;
                if (dp < dq || (dp == dq && s_pia[p] < s_pia[q])) { e = p; l = q; }
                else                                              { e = q; l = p; }
                const int iE = (int)s_pia[e], jE = (int)s_pja[e];
                const int iL = (int)s_pia[l], jL = (int)s_pja[l];
                const int szE1 = (int)s_sizes[iE], szE2 = (int)s_sizes[jE];
                const int szL1 = (int)s_sizes[iL], szL2 = (int)s_sizes[jL];
                const double siE = (double)szE1, sjE = (double)szE2;
                const double dE = g_nnd[iE];
                const double siL = (double)szL1, sjL = (double)szL2;
                const double dL = g_nnd[iL];
                const double a1c = g_d2[(size_t)iE * NPTS + iL];
                const double b1c = g_d2[(size_t)jE * NPTS + iL];
                const int T1 = szE1 + szE2 + szL1;
                const double u = div_exact((siE + siL) * a1c + (sjE + siL) * b1c - siL * dE,
                                           (double)T1, __ldg(&g_recip[T1]));
                const double a2c = g_d2[(size_t)iE * NPTS + jL];
                const double b2c = g_d2[(size_t)jE * NPTS + jL];
                const int T2 = szE1 + szE2 + szL2;
                const double v = div_exact((siE + sjL) * a2c + (sjE + sjL) * b2c - sjL * dE,
                                           (double)T2, __ldg(&g_recip[T2]));
                const double smE = siE + sjE;
                const int T3 = szL1 + szL2 + szE1 + szE2;
                const double nd = div_exact((siL + smE) * u + (sjL + smE) * v - smE * dL,
                                            (double)T3, __ldg(&g_recip[T3]));
                g_d2[(size_t)iE * NPTS + iL] = nd;
                g_d2[(size_t)iL * NPTS + iE] = nd;
            }
        }
        __syncthreads();

        // ---- post: sizes + stable alist compaction (block-local) ----
        {
            for (int p = t; p < np; p += NTH)
                s_sizes[(int)s_pia[p]] = (unsigned short)(s_sizes[(int)s_pia[p]] + s_sizes[(int)s_pja[p]]);
            const int i0 = 2 * t, i1 = 2 * t + 1;
            int c = 0;
            unsigned char k0 = 0, k1 = 0;
            if (i0 < na) {
                const int a = (int)s_alist[i0]; s_id[i0] = (short)a;
                const int b = g_nn[a];
                k0 = !((g_nn[b] == a) && (b < a));
                c += k0;
            }
            if (i1 < na) {
                const int a = (int)s_alist[i1]; s_id[i1] = (short)a;
                const int b = g_nn[a];
                k1 = !((g_nn[b] == a) && (b < a));
                c += k1;
            }
            s_a[t] = c;
            __syncthreads();
            int* src = s_a; int* dst = s_b;
            for (int off = 1; off < NTH; off <<= 1) {
                int v = src[t];
                if (t >= off) v += src[t - off];
                dst[t] = v;
                __syncthreads();
                int* tmp = src; src = dst; dst = tmp;
            }
            int pos = (t > 0) ? src[t - 1] : 0;
            if (i0 < na && k0) s_alist[pos++] = s_id[i0];
            if (i1 < na && k1) s_alist[pos] = s_id[i1];
            if (t == 0) s_na = src[NTH - 1];
            __syncthreads();
        }
        grid_bar();
    }

    // ================= all-smem slot endgame (block 0) =================
    if (blockIdx.x == 0) {
        const int na0 = s_na;
        // load slots
        if (t < EG) {
            const int id = (t < na0) ? (int)s_alist[t] : -1;
            eg_id[t] = (short)id;
            eg_sz[t] = (t < na0) ? (int)s_sizes[id] : 0;
            eg_live[t] = (t < na0) ? 1 : 0;
        }
        __syncthreads();
        for (int idx = t; idx < EG * EG; idx += NTH) {
            const int p = idx >> 6, q = idx & 63;
            sd2[p][q] = (p < na0 && q < na0)
                        ? g_d2[(size_t)(int)eg_id[p] * NPTS + (int)eg_id[q]] : INF;
        }
        if (t == 0) s_live = na0;
        __syncthreads();

        while (s_live > 1) {
            // NN per slot (warp per row; lane covers c, c+32)
            for (int r = w; r < EG; r += 32) {
                long long v0 = __double_as_longlong(sd2[r][lane]);
                long long v1 = __double_as_longlong(sd2[r][lane + 32]);
                long long bv; int bc;
                if (v1 < v0) { bv = v1; bc = lane + 32; } else { bv = v0; bc = lane; }
                #pragma unroll
                for (int o = 16; o > 0; o >>= 1) {
                    long long ov = __shfl_down_sync(0xffffffffu, bv, o);
                    int       oc = __shfl_down_sync(0xffffffffu, bc, o);
                    if (ov < bv || (ov == bv && oc < bc)) { bv = ov; bc = oc; }
                }
                if (lane == 0) { eg_nn[r] = bc; eg_nnd[r] = __longlong_as_double(bv); }
            }
            if (t == 0) s_np = 0;
            __syncthreads();

            // mutual pairs (slot order = id order -> same tie-breaks)
            if (t < EG) {
                unsigned char mg = 0;
                if (eg_live[t]) {
                    const int b = eg_nn[t];
                    if (b < EG && eg_nn[b] == t) {
                        mg = 1;
                        if (t < b) {
                            const int pos = atomicAdd(&s_np, 1);
                            eg_pia[pos] = (short)t; eg_pja[pos] = (short)b;
                        }
                    }
                }
                eg_mg[t] = mg;
            }
            __syncthreads();
            const int np = s_np;

            // merge log
            {
                const int mbase = g_mcnt;
                for (int p = t; p < np; p += NTH) {
                    const int ia = (int)eg_pia[p], ja = (int)eg_pja[p];
                    g_parent[(int)eg_id[ja]] = (int)eg_id[ia];
                    g_md[mbase + p] = eg_nnd[ia];
                    g_mj[mbase + p] = (int)eg_id[ja];
                }
                __syncthreads();
                if (t == 0) g_mcnt = mbase + np;
            }

            // LW (pair x slot), inf/NaN-safe for dead slots
            for (int idx = t; idx < np * EG; idx += NTH) {
                const int p = idx >> 6, m = idx & 63;
                if (eg_mg[m]) continue;
                const int ia = (int)eg_pia[p], ja = (int)eg_pja[p];
                const int szi = eg_sz[ia], szj = eg_sz[ja], szm = eg_sz[m];
                const double si = (double)szi, sj = (double)szj, sm = (double)szm;
                const double dij = eg_nnd[ia];
                const double a = sd2[ia][m], b = sd2[ja][m];
                int Ti = szi + szj + szm; if (Ti < 1) Ti = 1;
                const double num = ((si + sm) * a + (sj + sm) * b - sm * dij);
                const double nd = div_exact(num, (double)Ti, __ldg(&g_recip[Ti]));
                sd2[ia][m] = nd;
                sd2[m][ia] = nd;
            }
            // cross pairs
            for (int idx = t; idx < np * np; idx += NTH) {
                const int p = idx / np, q = idx - p * np;
                if (p >= q) continue;
                const double dp = eg_nnd[(int)eg_pia[p]], dq = eg_nnd[(int)eg_pia[q]];
                int e, l;
                if (dp < dq || (dp == dq && eg_pia[p] < eg_pia[q])) { e = p; l = q; }
                else                                                { e = q; l = p; }
                const int iE = (int)eg_pia[e], jE = (int)eg_pja[e];
                const int iL = (int)eg_pia[l], jL = (int)eg_pja[l];
                const int szE1 = eg_sz[iE], szE2 = eg_sz[jE];
                const int szL1 = eg_sz[iL], szL2 = eg_sz[jL];
                const double siE = (double)szE1, sjE = (double)szE2, dE = eg_nnd[iE];
                const double siL = (double)szL1, sjL = (double)szL2, dL = eg_nnd[iL];
                const int T1 = szE1 + szE2 + szL1;
                const double u = div_exact((siE + siL) * sd2[iE][iL] + (sjE + siL) * sd2[jE][iL] - siL * dE,
                                           (double)T1, __ldg(&g_recip[T1]));
                const int T2 = szE1 + szE2 + szL2;
                const double v = div_exact((siE + sjL) * sd2[iE][jL] + (sjE + sjL) * sd2[jE][jL] - sjL * dE,
                                           (double)T2, __ldg(&g_recip[T2]));
                const double smE = siE + sjE;
                const int T3 = szL1 + szL2 + szE1 + szE2;
                const double nd = div_exact((siL + smE) * u + (sjL + smE) * v - smE * dL,
                                            (double)T3, __ldg(&g_recip[T3]));
                sd2[iE][iL] = nd;
                sd2[iL][iE] = nd;
            }
            __syncthreads();

            // retire j-slots: sizes, live, inf rows/cols
            for (int p = t; p < np; p += NTH) {
                const int ia = (int)eg_pia[p], ja = (int)eg_pja[p];
                eg_sz[ia] += eg_sz[ja];
                eg_live[ja] = 0;
            }
            __syncthreads();
            for (int idx = t; idx < np * EG; idx += NTH) {
                const int p = idx >> 6, m = idx & 63;
                const int ja = (int)eg_pja[p];
                sd2[ja][m] = INF;
                sd2[m][ja] = INF;
            }
            if (t == 0) s_live -= np;
            __syncthreads();
        }

        // ---- tail: sort merge heights, cut, mark, ranks ----
        const int mc = g_mcnt;
        for (int i = t; i < NPTS; i += NTH) s_d[i] = (i < mc) ? g_md[i] : INF;
        __syncthreads();
        for (int k2 = 2; k2 <= NPTS; k2 <<= 1) {
            for (int jj = k2 >> 1; jj > 0; jj >>= 1) {
                for (int i = t; i < NPTS; i += NTH) {
                    const int ixj = i ^ jj;
                    if (ixj > i) {
                        const bool up = ((i & k2) == 0);
                        const double aa = s_d[i], bb = s_d[ixj];
                        if (up ? (aa > bb) : (aa < bb)) { s_d[i] = bb; s_d[ixj] = aa; }
                    }
                }
                __syncthreads();
            }
        }
        const double theta = s_d[NPTS - K - 1];
        for (int i = t; i < mc; i += NTH)
            if (g_md[i] <= theta) g_active[g_mj[i]] = 0;
        __syncthreads();
        const int e0 = g_active[2 * t], e1 = g_active[2 * t + 1];
        s_a[t] = e0 + e1;
        __syncthreads();
        int* src = s_a; int* dst = s_b;
        for (int off = 1; off < NTH; off <<= 1) {
            int v = src[t];
            if (t >= off) v += src[t - off];
            dst[t] = v;
            __syncthreads();
            int* tmp = src; src = dst; dst = tmp;
        }
        const int base = (t > 0) ? src[t - 1] : 0;
        g_rank[2 * t] = base;
        g_rank[2 * t + 1] = base + e0;
    }
    grid_bar();

    // ---- labels + one-hot writeout (all blocks) ----
    for (int p = gtid; p < NPTS; p += gstride) {
        int c = p;
        while (!g_active[c]) c = g_parent[c];
        const int lab = g_rank[c];
        float* o = out + (size_t)p * K;
        for (int q = 0; q < K; q++) o[q] = (q == lab) ? 1.0f : 0.0f;
    }
}

// ---------------------------------------------------------------------------
extern "C" void kernel_launch(void* const* d_in, const int* in_sizes, int n_in,
                              void* d_out, int out_size) {
    const float* x = (const float*)d_in[0];
    int K = out_size / NPTS;   // out = [B*N, K] one-hot => K from out_size

    static int nsm = 0;
    if (nsm == 0) {
        int v = 0;
        if (cudaDeviceGetAttribute(&v, cudaDevAttrMultiProcessorCount, 0) == cudaSuccess && v > 0)
            nsm = v;
        else
            nsm = 64;
    }

    k_init_sq<<<(NPTS + 255) / 256, 256>>>(x);
    k_init_d2<<<dim3(NPTS / TILE, NPTS / TILE), 256>>>(x);
    k_rnn<<<nsm, NTH>>>((float*)d_out, K);
}

// round 13
// speedup vs baseline: 1.1108x; 1.1108x over previous
#include <cuda_runtime.h>
#include <cuda_bf16.h>
#include <cstdint>

#define NPTS 2048
#define DIMS 96
#define NTH 1024
#define THRESH 64
#define EG 64
#define TILE 32
#define RECIPN (NPTS + 1)

// Device scratch (no runtime allocation allowed)
__device__ double g_d2[(size_t)NPTS * NPTS];      // 32 MB
__device__ double g_sq[NPTS];
__device__ long long g_sqi[NPTS];
__device__ unsigned g_k[NPTS * DIMS];             // x * 2^23 (exact integers)
__device__ int    g_exact;
__device__ double g_recip[RECIPN];
__device__ int    g_nn[NPTS];
__device__ double g_nnd[NPTS];
__device__ int    g_parent[NPTS];
__device__ int    g_active[NPTS];
__device__ int    g_rank[NPTS];
__device__ double g_md[NPTS];
__device__ int    g_mj[NPTS];
__device__ int    g_mcnt;
__device__ unsigned g_arrive;
__device__ volatile unsigned g_release;

__device__ __forceinline__ double dinf() {
    return __longlong_as_double(0x7ff0000000000000LL);
}

// Markstein correctly-rounded division num/T given r = RN(1/T): returns RN(num/T).
__device__ __forceinline__ double div_exact(double num, double T, double r) {
    double q0 = __dmul_rn(num, r);
    double e  = __fma_rn(-T, q0, num);
    return __fma_rn(e, r, q0);
}

// sense-reversal software grid barrier; waiters back off with nanosleep.
__device__ __forceinline__ void grid_bar() {
    __syncthreads();
    if (threadIdx.x == 0) {
        __threadfence();
        unsigned gen = g_release;
        if (atomicAdd(&g_arrive, 1) == gridDim.x - 1) {
            atomicExch(&g_arrive, 0);
            __threadfence();
            g_release = gen + 1;
        } else {
            while (g_release == gen) { __nanosleep(32); }
        }
        __threadfence();
    }
    __syncthreads();
}

// ---------------------------------------------------------------------------
// Init: staged-coalesced loads; serial fp64 per-point sums (bit-exact),
// integer lift + exactness check; misc bookkeeping. 32 blocks x 256 thr.
// ---------------------------------------------------------------------------
__global__ void k_init_sq(const float* __restrict__ x) {
    __shared__ float sx[64 * DIMS];          // 24 KB
    const int tid = threadIdx.x;
    const int g = blockIdx.x * 256 + tid;
    if (g < RECIPN) g_recip[g] = (g == 0) ? 1.0 : 1.0 / (double)g;
    if (g < NPTS) { g_parent[g] = g; g_active[g] = 1; }
    if (g == 0) { g_mcnt = 0; g_arrive = 0; g_release = 0; g_exact = 1; }

    const int base = blockIdx.x * 64 * DIMS;
    for (int idx = tid; idx < 64 * DIMS; idx += 256) sx[idx] = x[base + idx];
    __syncthreads();

    bool ok = true;
    for (int idx = tid; idx < 64 * DIMS; idx += 256) {
        const float xv = sx[idx];
        const unsigned k = (unsigned)(xv * 8388608.0f);
        if (k >= (1u << 23) || (float)k * (1.0f / 8388608.0f) != xv) ok = false;
        g_k[base + idx] = k;
    }
    if (!ok) atomicExch(&g_exact, 0);

    if (tid < 64) {
        const float* xr = sx + tid * DIMS;
        double acc = 0.0;
        long long acci = 0;
        #pragma unroll 8
        for (int d = 0; d < DIMS; d++) {
            const double v = (double)xr[d];
            acc = fma(v, v, acc);
            const long long k = (long long)(unsigned)(xr[d] * 8388608.0f);
            acci += k * k;
        }
        g_sq[blockIdx.x * 64 + tid] = acc;
        g_sqi[blockIdx.x * 64 + tid] = acci;
    }
}

// ---------------------------------------------------------------------------
// Distance matrix: exact int64 Gram fast path; proven fp64 fallback.
// ---------------------------------------------------------------------------
__global__ void k_init_d2(const float* __restrict__ x) {
    __shared__ unsigned SBUF[2][TILE][DIMS + 1];
    const int ti = blockIdx.y, tj = blockIdx.x;
    if (tj < ti) return;

    if (g_exact) {
        unsigned (*A)[DIMS + 1] = SBUF[0];
        unsigned (*B)[DIMS + 1] = SBUF[1];
        for (int idx = threadIdx.x; idx < TILE * DIMS; idx += blockDim.x) {
            const int r = idx / DIMS, d = idx - r * DIMS;
            A[r][d] = g_k[(size_t)(ti * TILE + r) * DIMS + d];
            B[r][d] = g_k[(size_t)(tj * TILE + r) * DIMS + d];
        }
        __syncthreads();
        const int r0 = (threadIdx.x >> 4) << 1;
        const int c0 = (threadIdx.x & 15) << 1;
        unsigned long long d00 = 0, d01 = 0, d10 = 0, d11 = 0;
        #pragma unroll 8
        for (int d = 0; d < DIMS; d++) {
            const unsigned a0 = A[r0][d], a1 = A[r0 + 1][d];
            const unsigned b0 = B[c0][d], b1 = B[c0 + 1][d];
            d00 += (unsigned long long)a0 * b0;
            d01 += (unsigned long long)a0 * b1;
            d10 += (unsigned long long)a1 * b0;
            d11 += (unsigned long long)a1 * b1;
        }
        #pragma unroll
        for (int rr = 0; rr < 2; rr++) {
            #pragma unroll
            for (int cc = 0; cc < 2; cc++) {
                const int gi = ti * TILE + r0 + rr;
                const int gj = tj * TILE + c0 + cc;
                if (gj < gi) continue;
                double v;
                if (gi == gj) v = dinf();
                else {
                    const unsigned long long dot =
                        (rr == 0) ? (cc == 0 ? d00 : d01) : (cc == 0 ? d10 : d11);
                    const long long num = g_sqi[gi] + g_sqi[gj] - 2ll * (long long)dot;
                    v = (double)num * 0x1p-46;
                }
                g_d2[(size_t)gi * NPTS + gj] = v;
                g_d2[(size_t)gj * NPTS + gi] = v;
            }
        }
    } else {
        float (*A)[DIMS + 1] = reinterpret_cast<float (*)[DIMS + 1]>(SBUF[0]);
        float (*B)[DIMS + 1] = reinterpret_cast<float (*)[DIMS + 1]>(SBUF[1]);
        for (int idx = threadIdx.x; idx < TILE * DIMS; idx += blockDim.x) {
            const int r = idx / DIMS, d = idx - r * DIMS;
            A[r][d] = x[(size_t)(ti * TILE + r) * DIMS + d];
            B[r][d] = x[(size_t)(tj * TILE + r) * DIMS + d];
        }
        __syncthreads();
        #pragma unroll
        for (int e = 0; e < (TILE * TILE) / 256; e++) {
            const int idx = threadIdx.x + e * 256;
            const int r = idx >> 5, c = idx & 31;
            const int gi = ti * TILE + r, gj = tj * TILE + c;
            if (gj < gi) continue;
            if (gi == gj) { g_d2[(size_t)gi * NPTS + gj] = dinf(); continue; }
            double dot = 0.0;
            #pragma unroll 8
            for (int d = 0; d < DIMS; d++) {
                dot = fma((double)A[r][d], (double)B[c][d], dot);
            }
            double v = g_sq[gi] + g_sq[gj] - 2.0 * dot;
            if (v < 0.0) v = 0.0;
            g_d2[(size_t)gi * NPTS + gj] = v;
            g_d2[(size_t)gj * NPTS + gi] = v;
        }
    }
}

// ---------------------------------------------------------------------------
// Persistent RNN-rounds kernel: incremental NN refresh + smem slot endgame.
// ---------------------------------------------------------------------------
__global__ void __launch_bounds__(NTH, 1) k_rnn(float* __restrict__ out, int K) {
    // Time-multiplexed pool (33280 B):
    //  grid : pia[0,2K) pja[2K,4K) mg[4K,6K) bmg[6K,8K) nn[8K,16K)
    //         a[16K,20K) b[20K,24K) id[24K,28K)
    //  endgame: sd2 doubles [0,33280)
    //  tail : s_d [0,16K) | a[16K) b[20K)
    __shared__ __align__(16) char POOL[EG * (EG + 1) * 8];
    __shared__ short s_alist[NPTS];                  // 4 KB
    __shared__ unsigned short s_sizes[NPTS];         // 4 KB
    __shared__ int   s_wcnt[64], s_woff[64];
    __shared__ int   s_np, s_na, s_live;
    __shared__ short  eg_id[EG];
    __shared__ int    eg_sz[EG];
    __shared__ int    eg_nn[EG];
    __shared__ double eg_nnd[EG];
    __shared__ unsigned char eg_live[EG], eg_mg[EG];
    __shared__ short  eg_pia[EG / 2], eg_pja[EG / 2];

    short* s_pia = (short*)POOL;
    short* s_pja = (short*)(POOL + 2048);
    unsigned char* s_mg  = (unsigned char*)(POOL + 4096);   // by position
    unsigned char* s_bmg = (unsigned char*)(POOL + 6144);   // by id
    int*   s_nn  = (int*)(POOL + 8192);                     // old NN by id
    double* s_d = (double*)POOL;
    int* s_a = (int*)(POOL + 16384);
    int* s_b = (int*)(POOL + 20480);
    short* s_id = (short*)(POOL + 24576);
    double (*sd2)[EG + 1] = (double (*)[EG + 1])POOL;

    const int t = threadIdx.x;
    const int w = t >> 5, lane = t & 31;
    const int gtid = blockIdx.x * NTH + t;
    const int gstride = gridDim.x * NTH;
    const int gwarp = blockIdx.x * 32 + w;
    const int nwarps = gridDim.x * 32;
    const double INF = dinf();

    for (int r = t; r < NPTS; r += NTH) { s_alist[r] = (short)r; s_sizes[r] = 1; }
    if (t == 0) s_na = NPTS;
    __syncthreads();

    // full NN scan of row m over current alist (int64-bit lexicographic min)
    auto full_scan = [&](int m, int na) {
        const double* row = g_d2 + (size_t)m * NPTS;
        long long bv = 0x7ff0000000000000LL; int bc = NPTS;
        #pragma unroll 4
        for (int c = lane; c < na; c += 32) {
            const int id = (int)s_alist[c];
            const long long v = __double_as_longlong(row[id]);
            if (v < bv || (v == bv && id < bc)) { bv = v; bc = id; }
        }
        #pragma unroll
        for (int o = 16; o > 0; o >>= 1) {
            long long ov = __shfl_down_sync(0xffffffffu, bv, o);
            int       oc = __shfl_down_sync(0xffffffffu, bc, o);
            if (ov < bv || (ov == bv && oc < bc)) { bv = ov; bc = oc; }
        }
        if (lane == 0) { g_nn[m] = bc; g_nnd[m] = __longlong_as_double(bv); }
    };

    // ---- bootstrap NN ----
    {
        const int na = s_na;
        for (int r = gwarp; r < na; r += nwarps) full_scan((int)s_alist[r], na);
    }
    grid_bar();

    // ================= grid-wide rounds =================
    while (true) {
        const int na = s_na;
        if (na <= THRESH) break;

        // ---- cache g_nn block-locally (coalesced) ----
        for (int idx = t; idx < NPTS; idx += NTH) s_nn[idx] = g_nn[idx];
        __syncthreads();

        // ---- pairs (redundant deterministic per block) ----
        {
            bool p0 = false, p1 = false;
            int a0 = 0, b0 = 0, a1 = 0, b1 = 0;
            if (t < na) {
                a0 = (int)s_alist[t]; b0 = s_nn[a0];
                const bool mut = (s_nn[b0] == a0);
                p0 = mut && (a0 < b0);
                s_mg[t] = (unsigned char)mut;
                s_bmg[a0] = (unsigned char)mut;
            }
            const int t2 = t + NTH;
            if (t2 < na) {
                a1 = (int)s_alist[t2]; b1 = s_nn[a1];
                const bool mut = (s_nn[b1] == a1);
                p1 = mut && (a1 < b1);
                s_mg[t2] = (unsigned char)mut;
                s_bmg[a1] = (unsigned char)mut;
            }
            const unsigned m0 = __ballot_sync(0xffffffffu, p0);
            const unsigned m1 = __ballot_sync(0xffffffffu, p1);
            if (lane == 0) { s_wcnt[w] = __popc(m0); s_wcnt[32 + w] = __popc(m1); }
            __syncthreads();
            if (t == 0) {
                int acc = 0;
                #pragma unroll
                for (int q = 0; q < 64; q++) { s_woff[q] = acc; acc += s_wcnt[q]; }
                s_np = acc;
            }
            __syncthreads();
            if (p0) {
                const int pos = s_woff[w] + __popc(m0 & ((1u << lane) - 1u));
                s_pia[pos] = (short)a0; s_pja[pos] = (short)b0;
            }
            if (p1) {
                const int pos = s_woff[32 + w] + __popc(m1 & ((1u << lane) - 1u));
                s_pia[pos] = (short)a1; s_pja[pos] = (short)b1;
            }
            __syncthreads();
        }
        const int np = s_np;

        if (blockIdx.x == 0) {
            const int mbase = g_mcnt;
            for (int p = t; p < np; p += NTH) {
                const int ia = (int)s_pia[p], ja = (int)s_pja[p];
                g_parent[ja] = ia;
                g_md[mbase + p] = g_nnd[ia];
                g_mj[mbase + p] = ja;
            }
            __syncthreads();
            if (t == 0) g_mcnt = mbase + np;
        }

        // ---- Lance-Williams: (pair x unmerged) + same-round cross ----
        {
            const long long tot1 = (long long)np * na;
            for (long long xw = gtid; xw < tot1; xw += gstride) {
                const int p = (int)(xw / na);
                const int idx = (int)(xw - (long long)p * na);
                if (s_mg[idx]) continue;
                const int m = (int)s_alist[idx];
                const int iA = (int)s_pia[p], jA = (int)s_pja[p];
                const int szi = (int)s_sizes[iA], szj = (int)s_sizes[jA], szm = (int)s_sizes[m];
                const double si = (double)szi, sj = (double)szj;
                const double dij = g_nnd[iA];
                const double sm = (double)szm;
                const double a = g_d2[(size_t)iA * NPTS + m];
                const double b = g_d2[(size_t)jA * NPTS + m];
                const int Ti = szi + szj + szm;
                const double num = ((si + sm) * a + (sj + sm) * b - sm * dij);
                const double nd = div_exact(num, (double)Ti, __ldg(&g_recip[Ti]));
                g_d2[(size_t)iA * NPTS + m] = nd;
                g_d2[(size_t)m * NPTS + iA] = nd;
            }
            const long long tot2 = (long long)np * np;
            for (long long xw = gtid; xw < tot2; xw += gstride) {
                const int p = (int)(xw / np);
                const int q = (int)(xw - (long long)p * np);
                if (p >= q) continue;
                const double dp = g_nnd[(int)s_pia[p]], dq = g_nnd[(int)s_pia[q]];
                int e, l;
                if (dp < dq || (dp == dq && s_pia[p] < s_pia[q])) { e = p; l = q; }
                else                                              { e = q; l = p; }
                const int iE = (int)s_pia[e], jE = (int)s_pja[e];
                const int iL = (int)s_pia[l], jL = (int)s_pja[l];
                const int szE1 = (int)s_sizes[iE], szE2 = (int)s_sizes[jE];
                const int szL1 = (int)s_sizes[iL], szL2 = (int)s_sizes[jL];
                const double siE = (double)szE1, sjE = (double)szE2;
                const double dE = g_nnd[iE];
                const double siL = (double)szL1, sjL = (double)szL2;
                const double dL = g_nnd[iL];
                const double a1c = g_d2[(size_t)iE * NPTS + iL];
                const double b1c = g_d2[(size_t)jE * NPTS + iL];
                const int T1 = szE1 + szE2 + szL1;
                const double u = div_exact((siE + siL) * a1c + (sjE + siL) * b1c - siL * dE,
                                           (double)T1, __ldg(&g_recip[T1]));
                const double a2c = g_d2[(size_t)iE * NPTS + jL];
                const double b2c = g_d2[(size_t)jE * NPTS + jL];
                const int T2 = szE1 + szE2 + szL2;
                const double v = div_exact((siE + sjL) * a2c + (sjE + sjL) * b2c - sjL * dE,
                                           (double)T2, __ldg(&g_recip[T2]));
                const double smE = siE + sjE;
                const int T3 = szL1 + szL2 + szE1 + szE2;
                const double nd = div_exact((siL + smE) * u + (sjL + smE) * v - smE * dL,
                                            (double)T3, __ldg(&g_recip[T3]));
                g_d2[(size_t)iE * NPTS + iL] = nd;
                g_d2[(size_t)iL * NPTS + iE] = nd;
            }
        }
        __syncthreads();

        // ---- post: sizes + stable alist compaction (block-local) ----
        {
            for (int p = t; p < np; p += NTH)
                s_sizes[(int)s_pia[p]] = (unsigned short)(s_sizes[(int)s_pia[p]] + s_sizes[(int)s_pja[p]]);
            const int i0 = 2 * t, i1 = 2 * t + 1;
            int c = 0;
            unsigned char k0 = 0, k1 = 0;
            if (i0 < na) {
                const int a = (int)s_alist[i0]; s_id[i0] = (short)a;
                const int b = s_nn[a];
                k0 = !((s_nn[b] == a) && (b < a));
                c += k0;
            }
            if (i1 < na) {
                const int a = (int)s_alist[i1]; s_id[i1] = (short)a;
                const int b = s_nn[a];
                k1 = !((s_nn[b] == a) && (b < a));
                c += k1;
            }
            s_a[t] = c;
            __syncthreads();
            int* src = s_a; int* dst = s_b;
            for (int off = 1; off < NTH; off <<= 1) {
                int v = src[t];
                if (t >= off) v += src[t - off];
                dst[t] = v;
                __syncthreads();
                int* tmp = src; src = dst; dst = tmp;
            }
            int pos = (t > 0) ? src[t - 1] : 0;
            if (i0 < na && k0) s_alist[pos++] = s_id[i0];
            if (i1 < na && k1) s_alist[pos] = s_id[i1];
            if (t == 0) s_na = src[NTH - 1];
            __syncthreads();
        }
        grid_bar();   // d2 + new alist consistent everywhere

        // ---- NN refresh over NEW alist ----
        {
            const int na2 = s_na;
            for (int r = gwarp; r < na2; r += nwarps) {
                const int m = (int)s_alist[r];
                const int oldnn = s_nn[m];
                if (s_bmg[oldnn]) {
                    full_scan(m, na2);          // cached argmin merged -> rescan
                } else {
                    // incremental: old (rowmin,argmin) + np fresh i-columns
                    long long bv = __double_as_longlong(g_nnd[m]);
                    int bc = oldnn;
                    const double* row = g_d2 + (size_t)m * NPTS;
                    #pragma unroll 4
                    for (int p = lane; p < np; p += 32) {
                        const int id = (int)s_pia[p];
                        const long long v = __double_as_longlong(row[id]);
                        if (v < bv || (v == bv && id < bc)) { bv = v; bc = id; }
                    }
                    #pragma unroll
                    for (int o = 16; o > 0; o >>= 1) {
                        long long ov = __shfl_down_sync(0xffffffffu, bv, o);
                        int       oc = __shfl_down_sync(0xffffffffu, bc, o);
                        if (ov < bv || (ov == bv && oc < bc)) { bv = ov; bc = oc; }
                    }
                    if (lane == 0) { g_nn[m] = bc; g_nnd[m] = __longlong_as_double(bv); }
                }
            }
        }
        grid_bar();   // g_nn visible for next round
    }

    // ================= all-smem slot endgame (block 0) =================
    if (blockIdx.x == 0) {
        const int na0 = s_na;
        if (t < EG) {
            const int id = (t < na0) ? (int)s_alist[t] : -1;
            eg_id[t] = (short)id;
            eg_sz[t] = (t < na0) ? (int)s_sizes[id] : 0;
            eg_live[t] = (t < na0) ? 1 : 0;
        }
        __syncthreads();
        for (int idx = t; idx < EG * EG; idx += NTH) {
            const int p = idx >> 6, q = idx & 63;
            sd2[p][q] = (p < na0 && q < na0)
                        ? g_d2[(size_t)(int)eg_id[p] * NPTS + (int)eg_id[q]] : INF;
        }
        if (t == 0) s_live = na0;
        __syncthreads();

        while (s_live > 1) {
            for (int r = w; r < EG; r += 32) {
                long long v0 = __double_as_longlong(sd2[r][lane]);
                long long v1 = __double_as_longlong(sd2[r][lane + 32]);
                long long bv; int bc;
                if (v1 < v0) { bv = v1; bc = lane + 32; } else { bv = v0; bc = lane; }
                #pragma unroll
                for (int o = 16; o > 0; o >>= 1) {
                    long long ov = __shfl_down_sync(0xffffffffu, bv, o);
                    int       oc = __shfl_down_sync(0xffffffffu, bc, o);
                    if (ov < bv || (ov == bv && oc < bc)) { bv = ov; bc = oc; }
                }
                if (lane == 0) { eg_nn[r] = bc; eg_nnd[r] = __longlong_as_double(bv); }
            }
            if (t == 0) s_np = 0;
            __syncthreads();

            if (t < EG) {
                unsigned char mg = 0;
                if (eg_live[t]) {
                    const int b = eg_nn[t];
                    if (b < EG && eg_nn[b] == t) {
                        mg = 1;
                        if (t < b) {
                            const int pos = atomicAdd(&s_np, 1);
                            eg_pia[pos] = (short)t; eg_pja[pos] = (short)b;
                        }
                    }
                }
                eg_mg[t] = mg;
            }
            __syncthreads();
            const int np = s_np;

            {
                const int mbase = g_mcnt;
                for (int p = t; p < np; p += NTH) {
                    const int ia = (int)eg_pia[p], ja = (int)eg_pja[p];
                    g_parent[(int)eg_id[ja]] = (int)eg_id[ia];
                    g_md[mbase + p] = eg_nnd[ia];
                    g_mj[mbase + p] = (int)eg_id[ja];
                }
                __syncthreads();
                if (t == 0) g_mcnt = mbase + np;
            }

            for (int idx = t; idx < np * EG; idx += NTH) {
                const int p = idx >> 6, m = idx & 63;
                if (eg_mg[m]) continue;
                const int ia = (int)eg_pia[p], ja = (int)eg_pja[p];
                const int szi = eg_sz[ia], szj = eg_sz[ja], szm = eg_sz[m];
                const double si = (double)szi, sj = (double)szj, sm = (double)szm;
                const double dij = eg_nnd[ia];
                const double a = sd2[ia][m], b = sd2[ja][m];
                int Ti = szi + szj + szm; if (Ti < 1) Ti = 1;
                const double num = ((si + sm) * a + (sj + sm) * b - sm * dij);
                const double nd = div_exact(num, (double)Ti, __ldg(&g_recip[Ti]));
                sd2[ia][m] = nd;
                sd2[m][ia] = nd;
            }
            for (int idx = t; idx < np * np; idx += NTH) {
                const int p = idx / np, q = idx - p * np;
                if (p >= q) continue;
                const double dp = eg_nnd[(int)eg_pia[p]], dq = eg_nnd[(int)eg_pia[q]];
                int e, l;
                if (dp < dq || (dp == dq && eg_pia[p] < eg_pia[q])) { e = p; l = q; }
                else                                                { e = q; l = p; }
                const int iE = (int)eg_pia[e], jE = (int)eg_pja[e];
                const int iL = (int)eg_pia[l], jL = (int)eg_pja[l];
                const int szE1 = eg_sz[iE], szE2 = eg_sz[jE];
                const int szL1 = eg_sz[iL], szL2 = eg_sz[jL];
                const double siE = (double)szE1, sjE = (double)szE2, dE = eg_nnd[iE];
                const double siL = (double)szL1, sjL = (double)szL2, dL = eg_nnd[iL];
                const int T1 = szE1 + szE2 + szL1;
                const double u = div_exact((siE + siL) * sd2[iE][iL] + (sjE + siL) * sd2[jE][iL] - siL * dE,
                                           (double)T1, __ldg(&g_recip[T1]));
                const int T2 = szE1 + szE2 + szL2;
                const double v = div_exact((siE + sjL) * sd2[iE][jL] + (sjE + sjL) * sd2[jE][jL] - sjL * dE,
                                           (double)T2, __ldg(&g_recip[T2]));
                const double smE = siE + sjE;
                const int T3 = szL1 + szL2 + szE1 + szE2;
                const double nd = div_exact((siL + smE) * u + (sjL + smE) * v - smE * dL,
                                            (double)T3, __ldg(&g_recip[T3]));
                sd2[iE][iL] = nd;
                sd2[iL][iE] = nd;
            }
            __syncthreads();

            for (int p = t; p < np; p += NTH) {
                const int ia = (int)eg_pia[p], ja = (int)eg_pja[p];
                eg_sz[ia] += eg_sz[ja];
                eg_live[ja] = 0;
            }
            __syncthreads();
            for (int idx = t; idx < np * EG; idx += NTH) {
                const int p = idx >> 6, m = idx & 63;
                const int ja = (int)eg_pja[p];
                sd2[ja][m] = INF;
                sd2[m][ja] = INF;
            }
            if (t == 0) s_live -= np;
            __syncthreads();
        }

        // ---- tail: sort merge heights, cut, mark, ranks ----
        const int mc = g_mcnt;
        for (int i = t; i < NPTS; i += NTH) s_d[i] = (i < mc) ? g_md[i] : INF;
        __syncthreads();
        for (int k2 = 2; k2 <= NPTS; k2 <<= 1) {
            for (int jj = k2 >> 1; jj > 0; jj >>= 1) {
                for (int i = t; i < NPTS; i += NTH) {
                    const int ixj = i ^ jj;
                    if (ixj > i) {
                        const bool up = ((i & k2) == 0);
                        const double aa = s_d[i], bb = s_d[ixj];
                        if (up ? (aa > bb) : (aa < bb)) { s_d[i] = bb; s_d[ixj] = aa; }
                    }
                }
                __syncthreads();
            }
        }
        const double theta = s_d[NPTS - K - 1];
        for (int i = t; i < mc; i += NTH)
            if (g_md[i] <= theta) g_active[g_mj[i]] = 0;
        __syncthreads();
        const int e0 = g_active[2 * t], e1 = g_active[2 * t + 1];
        s_a[t] = e0 + e1;
        __syncthreads();
        int* src = s_a; int* dst = s_b;
        for (int off = 1; off < NTH; off <<= 1) {
            int v = src[t];
            if (t >= off) v += src[t - off];
            dst[t] = v;
            __syncthreads();
            int* tmp = src; src = dst; dst = tmp;
        }
        const int base = (t > 0) ? src[t - 1] : 0;
        g_rank[2 * t] = base;
        g_rank[2 * t + 1] = base + e0;
    }
    grid_bar();

    // ---- labels + one-hot writeout (all blocks) ----
    for (int p = gtid; p < NPTS; p += gstride) {
        int c = p;
        while (!g_active[c]) c = g_parent[c];
        const int lab = g_rank[c];
        float* o = out + (size_t)p * K;
        for (int q = 0; q < K; q++) o[q] = (q == lab) ? 1.0f : 0.0f;
    }
}

// ---------------------------------------------------------------------------
extern "C" void kernel_launch(void* const* d_in, const int* in_sizes, int n_in,
                              void* d_out, int out_size) {
    const float* x = (const float*)d_in[0];
    int K = out_size / NPTS;   // out = [B*N, K] one-hot => K from out_size

    static int nsm = 0;
    if (nsm == 0) {
        int v = 0;
        if (cudaDeviceGetAttribute(&v, cudaDevAttrMultiProcessorCount, 0) == cudaSuccess && v > 0)
            nsm = v;
        else
            nsm = 64;
    }

    k_init_sq<<<NPTS / 64, 256>>>(x);
    k_init_d2<<<dim3(NPTS / TILE, NPTS / TILE), 256>>>(x);
    k_rnn<<<nsm, NTH>>>((float*)d_out, K);
}